// round 16
// baseline (speedup 1.0000x reference)
#include <cuda_runtime.h>
#include <math.h>

#define N_B   1024
#define N_S   4096
#define N_G   60
#define EMB   64
#define LDST  66          // smem row stride in floats (264B): conflict-free LDS.64 pattern

typedef unsigned long long ull;

// per-block partial sums: .x = positive-term sum, .y = negative-term sum
// blocks [0,1024) = species tiles, [1024,1088) = genus tiles. Every block writes
// its slot unconditionally each replay -> no zeroing, no atomics, deterministic.
__device__ float2 g_part[1088];

__device__ __forceinline__ float warpsum(float v) {
#pragma unroll
    for (int o = 16; o; o >>= 1) v += __shfl_xor_sync(0xffffffffu, v, o);
    return v;
}
__device__ __forceinline__ double warpsumd(double v) {
#pragma unroll
    for (int o = 16; o; o >>= 1) v += __shfl_xor_sync(0xffffffffu, v, o);
    return v;
}
__device__ __forceinline__ int warpord(int v) {
#pragma unroll
    for (int o = 16; o; o >>= 1) v += __shfl_xor_sync(0xffffffffu, v, o);
    return v;
}

// ---------------------------------------------------------------------------
// fused mobius-dist -> softplus epilogue (validated at rel_err 1.3e-7)
// ---------------------------------------------------------------------------
__device__ __forceinline__ void pair_acc(float dotxy, float a2, float y2,
                                         bool matched, float& Spos, float& Sneg)
{
    const float Cc = 0.1f;
    float m      = -dotxy;
    float coef_a = 1.0f + 0.2f * m + Cc * y2;
    float coef_y = 1.0f - Cc * a2;
    float num2   = (coef_a * coef_a) * a2
                 + (2.0f * coef_a * coef_y) * m
                 + (coef_y * coef_y) * y2;
    float denom  = 1.0f + 0.2f * m + 0.01f * (a2 * y2);
    float dd     = fmaxf(fabsf(denom), 1e-15f);
    float n      = sqrtf(fmaxf(num2, 0.0f) * Cc);       // sc * ||num||
    n            = fminf(n, (1.0f - 1e-5f) * dd);       // arg clip
    float u      = __fdividef(dd + n, dd - n);          // (1+t)/(1-t)
    float Lu     = __log2f(u);
    float d      = Lu * 2.1919238f;                     // ln2 / sqrt(0.1)
    float spn    = __logf(1.0f + __expf(-d));           // softplus(-d), d >= 0
    if (matched) Spos += d + spn;
    else         Sneg += spn;
}

// ---------------------------------------------------------------------------
// k_main: 1088 blocks, 256 threads.
//   blocks [0,1024): species tiles (64 batch x 64 species), prep folded in.
//   blocks [1024,1088): genus tiles (64 species x 60 genus), prep folded in.
// GEMM: 4x4 strided register tile, f32x2-packed over k, conflict-free LDS.64.
// ---------------------------------------------------------------------------
__global__ __launch_bounds__(256) void k_main(const float* __restrict__ X,
                                              const int* __restrict__ Tsp,
                                              const int* __restrict__ s2g,
                                              const float* __restrict__ gtan,
                                              const float* __restrict__ stan)
{
    __shared__ float shA[64 * LDST];
    __shared__ float shB[64 * LDST];
    __shared__ float shA2[64], shB2[64];
    __shared__ int   shTi[64];
    __shared__ int   shPr[64];
    __shared__ int   shTsp[N_B];
    __shared__ float red[16];

    const int  tid = threadIdx.x;
    const bool gen = (blockIdx.x >= 1024);

    const float *srcA, *srcB;
    int nB, s0;
    if (!gen) {
        int by = blockIdx.x >> 6, bx = blockIdx.x & 63;
        s0   = bx * 64;
        srcA = X + (by * 64) * EMB;       // X tile (not projected)
        srcB = stan + s0 * EMB;           // species proxies (project)
        nB   = 64;
    } else {
        s0   = (blockIdx.x - 1024) * 64;
        srcA = stan + s0 * EMB;           // species proxies (project)
        srcB = gtan;                      // genus proxies (project), 60 rows
        nB   = N_G;
    }

    // ---- load tiles as float2 (coalesced LDG.64 / conflict-free STS.64) ----
#pragma unroll
    for (int i = 0; i < 8; i++) {
        int idx = tid + i * 256;
        int r = idx >> 5, c2 = (idx & 31) * 2;
        *(float2*)&shA[r * LDST + c2] = *(const float2*)(srcA + r * EMB + c2);
        float2 w = make_float2(0.0f, 0.0f);
        if (r < nB) w = *(const float2*)(srcB + r * EMB + c2);
        *(float2*)&shB[r * LDST + c2] = w;
    }
    if (!gen) {
        if (tid < 64) shTi[tid] = Tsp[(blockIdx.x >> 6) * 64 + tid];
    } else {
        if (tid < 64) shTi[tid] = s2g[s0 + tid];
#pragma unroll
        for (int i = 0; i < 4; i++) shTsp[tid + i * 256] = Tsp[tid + i * 256];
    }
    __syncthreads();

    // ---- per-row norms / in-place projections (quad of threads per row) ----
    // Analytic simplification: n2 = min(max(||x||,1e-5), 2.3), th = tanh(sc*n2),
    // y = x * [min(1,2.3/n) * th/(sc*n2)], ||y||^2 = th^2/c  (maxnorm branch
    // provably never fires since th <= tanh(0.727) = 0.62 < 0.999).
    {
        const float SC = 0.31622776601683794f;
        int row = tid >> 2, q = tid & 3;
        int base = row * LDST + q * 16;

        float sa = 0.0f;
#pragma unroll
        for (int c = 0; c < 16; c++) { float v = shA[base + c]; sa = fmaf(v, v, sa); }
        sa += __shfl_xor_sync(0xffffffffu, sa, 1);
        sa += __shfl_xor_sync(0xffffffffu, sa, 2);
        if (!gen) {
            if (q == 0) shA2[row] = sa;   // raw ||X_b||^2
        } else {
            float nn  = fmaxf(sqrtf(sa), 1e-5f);
            float n2  = fminf(nn, 2.3f);
            float scn = SC * n2;
            float th  = tanhf(scn);
            float f   = __fdividef(th, scn) * fminf(1.0f, __fdividef(2.3f, nn));
#pragma unroll
            for (int c = 0; c < 16; c++) shA[base + c] *= f;
            if (q == 0) shA2[row] = th * th * 10.0f;
        }

        float sb = 0.0f;
#pragma unroll
        for (int c = 0; c < 16; c++) { float v = shB[base + c]; sb = fmaf(v, v, sb); }
        sb += __shfl_xor_sync(0xffffffffu, sb, 1);
        sb += __shfl_xor_sync(0xffffffffu, sb, 2);
        {
            float nn  = fmaxf(sqrtf(sb), 1e-5f);
            float n2  = fminf(nn, 2.3f);
            float scn = SC * n2;
            float th  = tanhf(scn);
            float f   = __fdividef(th, scn) * fminf(1.0f, __fdividef(2.3f, nn));
#pragma unroll
            for (int c = 0; c < 16; c++) shB[base + c] *= f;
            if (q == 0) shB2[row] = th * th * 10.0f;
        }

        if (gen) {
            // present[row] = any(Tsp == s0+row); quad splits the 1024 scan
            int target = s0 + row;
            int fnd = 0;
            const int* p = &shTsp[q * 256];
            for (int t = 0; t < 256; t++) fnd |= (p[t] == target);
            fnd |= __shfl_xor_sync(0xffffffffu, fnd, 1);
            fnd |= __shfl_xor_sync(0xffffffffu, fnd, 2);
            if (q == 0) shPr[row] = fnd;
        }
    }
    __syncthreads();

    // ---- GEMM: thread (tx,ty) owns rows {ty+16i}, cols {tx+16j}, f32x2 over k
    const int tx = tid & 15, ty = tid >> 4;
    ull acc[16];
#pragma unroll
    for (int u = 0; u < 16; u++) acc[u] = 0ull;

    const float* pa = shA + ty * LDST;
    const float* pb = shB + tx * LDST;
#pragma unroll 8
    for (int kk = 0; kk < 32; kk++) {
        ull a[4], b[4];
#pragma unroll
        for (int i = 0; i < 4; i++) a[i] = *(const ull*)(pa + i * 16 * LDST + 2 * kk);
#pragma unroll
        for (int j = 0; j < 4; j++) b[j] = *(const ull*)(pb + j * 16 * LDST + 2 * kk);
#pragma unroll
        for (int i = 0; i < 4; i++)
#pragma unroll
            for (int j = 0; j < 4; j++)
                asm("fma.rn.f32x2 %0, %1, %2, %0;"
                    : "+l"(acc[i * 4 + j]) : "l"(a[i]), "l"(b[j]));
    }

    // ---- epilogue ----
    float S1 = 0.0f, S2 = 0.0f;
#pragma unroll
    for (int i = 0; i < 4; i++) {
        int rl = ty + 16 * i;
        float a2 = shA2[rl];
        int   ti = shTi[rl];
        int   pr = gen ? shPr[rl] : 1;
#pragma unroll
        for (int j = 0; j < 4; j++) {
            int cl = tx + 16 * j;
            float lo, hi;
            asm("mov.b64 {%0, %1}, %2;" : "=f"(lo), "=f"(hi) : "l"(acc[i * 4 + j]));
            float dot = lo + hi;
            bool active  = gen ? (pr && cl < N_G) : true;
            bool matched = gen ? (ti == cl) : (ti == s0 + cl);
            if (active) pair_acc(dot, a2, shB2[cl], matched, S1, S2);
        }
    }
    S1 = warpsum(S1); S2 = warpsum(S2);
    int w = tid >> 5;
    if ((tid & 31) == 0) { red[w] = S1; red[w + 8] = S2; }
    __syncthreads();
    if (tid == 0) {
        float a = 0.0f, b = 0.0f;
#pragma unroll
        for (int q = 0; q < 8; q++) { a += red[q]; b += red[q + 8]; }
        g_part[blockIdx.x] = make_float2(a, b);
    }
}

// ---------------------------------------------------------------------------
// k_final: nvs = |{Tsp}|, nvg = |{s2g[Tsp]}| via shared bitmaps; deterministic
// double reduction of the 1088 per-block partials; write scalar loss.
// ---------------------------------------------------------------------------
__global__ void k_final(const int* __restrict__ Tsp, const int* __restrict__ s2g,
                        float* __restrict__ out)
{
    __shared__ unsigned int bm[128];
    __shared__ unsigned int bg[2];
    __shared__ double dr1[8], dr2[8], dr3[8], dr4[8];

    int tid = threadIdx.x;
    if (tid < 128) bm[tid] = 0u;
    if (tid < 2)   bg[tid] = 0u;
    __syncthreads();

    for (int b = tid; b < N_B; b += 256) {
        int s = Tsp[b];
        atomicOr(&bm[s >> 5], 1u << (s & 31));
        int g = s2g[s];
        atomicOr(&bg[g >> 5], 1u << (g & 31));
    }
    __syncthreads();

    double s1 = 0.0, s2 = 0.0, s3 = 0.0, s4 = 0.0;
    for (int i = tid; i < 1024; i += 256) {
        float2 v = g_part[i];
        s1 += (double)v.x; s2 += (double)v.y;
    }
    if (tid < 64) {
        float2 v = g_part[1024 + tid];
        s3 = (double)v.x; s4 = (double)v.y;
    }
    s1 = warpsumd(s1); s2 = warpsumd(s2);
    s3 = warpsumd(s3); s4 = warpsumd(s4);
    int w = tid >> 5;
    if ((tid & 31) == 0) { dr1[w] = s1; dr2[w] = s2; dr3[w] = s3; dr4[w] = s4; }
    __syncthreads();

    if (tid == 0) {
        double a1 = 0, a2 = 0, a3 = 0, a4 = 0;
#pragma unroll
        for (int q = 0; q < 8; q++) { a1 += dr1[q]; a2 += dr2[q]; a3 += dr3[q]; a4 += dr4[q]; }
        int nvs = 0;
        for (int q = 0; q < 128; q++) nvs += __popc(bm[q]);
        int nvg = __popc(bg[0]) + __popc(bg[1]);
        double loss = a1 / fmax((double)nvs, 1.0)
                    + a2 / (double)N_S
                    + a3 / fmax((double)nvg, 1.0)
                    + a4 / (double)N_G;
        out[0] = (float)loss;
    }
}

// ---------------------------------------------------------------------------
extern "C" void kernel_launch(void* const* d_in, const int* in_sizes, int n_in,
                              void* d_out, int out_size)
{
    (void)in_sizes; (void)n_in; (void)out_size;
    const float* X    = (const float*)d_in[0];
    const int*   Tsp  = (const int*)  d_in[1];
    // d_in[2] = T_genus (unused by the loss)
    const int*   s2g  = (const int*)  d_in[3];
    const float* gtan = (const float*)d_in[4];
    const float* stan = (const float*)d_in[5];

    k_main<<<1024 + 64, 256>>>(X, Tsp, s2g, gtan, stan);
    k_final<<<1, 256>>>(Tsp, s2g, (float*)d_out);
}

// round 17
// speedup vs baseline: 1.0229x; 1.0229x over previous
#include <cuda_runtime.h>
#include <math.h>

#define N_B   1024
#define N_S   4096
#define N_G   60
#define EMB   64
#define LDST  66          // smem row stride in floats (264B): conflict-free LDS.64 pattern

typedef unsigned long long ull;

// per-block partial sums: .x = positive-term sum, .y = negative-term sum
// blocks [0,1024) = species tiles, [1024,1088) = genus tiles. Every block writes
// its slot unconditionally each replay -> no zeroing, no atomics, deterministic.
__device__ float2 g_part[1088];

__device__ __forceinline__ float warpsum(float v) {
#pragma unroll
    for (int o = 16; o; o >>= 1) v += __shfl_xor_sync(0xffffffffu, v, o);
    return v;
}
__device__ __forceinline__ double warpsumd(double v) {
#pragma unroll
    for (int o = 16; o; o >>= 1) v += __shfl_xor_sync(0xffffffffu, v, o);
    return v;
}
__device__ __forceinline__ int warpord(int v) {
#pragma unroll
    for (int o = 16; o; o >>= 1) v += __shfl_xor_sync(0xffffffffu, v, o);
    return v;
}

// ---------------------------------------------------------------------------
// fused mobius-dist -> softplus epilogue (validated at rel_err 1.3e-7)
// ---------------------------------------------------------------------------
__device__ __forceinline__ void pair_acc(float dotxy, float a2, float y2,
                                         bool matched, float& Spos, float& Sneg)
{
    const float Cc = 0.1f;
    float m      = -dotxy;
    float coef_a = 1.0f + 0.2f * m + Cc * y2;
    float coef_y = 1.0f - Cc * a2;
    float num2   = (coef_a * coef_a) * a2
                 + (2.0f * coef_a * coef_y) * m
                 + (coef_y * coef_y) * y2;
    float denom  = 1.0f + 0.2f * m + 0.01f * (a2 * y2);
    float dd     = fmaxf(fabsf(denom), 1e-15f);
    float n      = sqrtf(fmaxf(num2, 0.0f) * Cc);       // sc * ||num||
    n            = fminf(n, (1.0f - 1e-5f) * dd);       // arg clip
    float u      = __fdividef(dd + n, dd - n);          // (1+t)/(1-t)
    float Lu     = __log2f(u);
    float d      = Lu * 2.1919238f;                     // ln2 / sqrt(0.1)
    float spn    = __logf(1.0f + __expf(-d));           // softplus(-d), d >= 0
    if (matched) Spos += d + spn;
    else         Sneg += spn;
}

// ---------------------------------------------------------------------------
// k_main: 1088 blocks, 256 threads.
//   blocks [0,1024): species tiles (64 batch x 64 species), prep folded in.
//   blocks [1024,1088): genus tiles (64 species x 60 genus), prep folded in.
// GEMM: 4x4 strided register tile, f32x2-packed over k, conflict-free LDS.64.
// ---------------------------------------------------------------------------
__global__ __launch_bounds__(256) void k_main(const float* __restrict__ X,
                                              const int* __restrict__ Tsp,
                                              const int* __restrict__ s2g,
                                              const float* __restrict__ gtan,
                                              const float* __restrict__ stan)
{
    __shared__ float shA[64 * LDST];
    __shared__ float shB[64 * LDST];
    __shared__ float shA2[64], shB2[64];
    __shared__ int   shTi[64];
    __shared__ int   shPr[64];
    __shared__ int   shTsp[N_B];
    __shared__ float red[16];

    const int  tid = threadIdx.x;
    const bool gen = (blockIdx.x >= 1024);

    const float *srcA, *srcB;
    int nB, s0;
    if (!gen) {
        int by = blockIdx.x >> 6, bx = blockIdx.x & 63;
        s0   = bx * 64;
        srcA = X + (by * 64) * EMB;       // X tile (not projected)
        srcB = stan + s0 * EMB;           // species proxies (project)
        nB   = 64;
    } else {
        s0   = (blockIdx.x - 1024) * 64;
        srcA = stan + s0 * EMB;           // species proxies (project)
        srcB = gtan;                      // genus proxies (project), 60 rows
        nB   = N_G;
    }

    // ---- load tiles as float2 (coalesced LDG.64 / conflict-free STS.64) ----
#pragma unroll
    for (int i = 0; i < 8; i++) {
        int idx = tid + i * 256;
        int r = idx >> 5, c2 = (idx & 31) * 2;
        *(float2*)&shA[r * LDST + c2] = *(const float2*)(srcA + r * EMB + c2);
        float2 w = make_float2(0.0f, 0.0f);
        if (r < nB) w = *(const float2*)(srcB + r * EMB + c2);
        *(float2*)&shB[r * LDST + c2] = w;
    }
    if (!gen) {
        if (tid < 64) shTi[tid] = Tsp[(blockIdx.x >> 6) * 64 + tid];
    } else {
        if (tid < 64) shTi[tid] = s2g[s0 + tid];
#pragma unroll
        for (int i = 0; i < 4; i++) shTsp[tid + i * 256] = Tsp[tid + i * 256];
    }
    __syncthreads();

    // ---- per-row norms / in-place projections (quad of threads per row) ----
    // Analytic simplification: n2 = min(max(||x||,1e-5), 2.3), th = tanh(sc*n2),
    // y = x * [min(1,2.3/n) * th/(sc*n2)], ||y||^2 = th^2/c  (maxnorm branch
    // provably never fires since th <= tanh(0.727) = 0.62 < 0.999).
    {
        const float SC = 0.31622776601683794f;
        int row = tid >> 2, q = tid & 3;
        int base = row * LDST + q * 16;

        float sa = 0.0f;
#pragma unroll
        for (int c = 0; c < 16; c++) { float v = shA[base + c]; sa = fmaf(v, v, sa); }
        sa += __shfl_xor_sync(0xffffffffu, sa, 1);
        sa += __shfl_xor_sync(0xffffffffu, sa, 2);
        if (!gen) {
            if (q == 0) shA2[row] = sa;   // raw ||X_b||^2
        } else {
            float nn  = fmaxf(sqrtf(sa), 1e-5f);
            float n2  = fminf(nn, 2.3f);
            float scn = SC * n2;
            float th  = tanhf(scn);
            float f   = __fdividef(th, scn) * fminf(1.0f, __fdividef(2.3f, nn));
#pragma unroll
            for (int c = 0; c < 16; c++) shA[base + c] *= f;
            if (q == 0) shA2[row] = th * th * 10.0f;
        }

        float sb = 0.0f;
#pragma unroll
        for (int c = 0; c < 16; c++) { float v = shB[base + c]; sb = fmaf(v, v, sb); }
        sb += __shfl_xor_sync(0xffffffffu, sb, 1);
        sb += __shfl_xor_sync(0xffffffffu, sb, 2);
        {
            float nn  = fmaxf(sqrtf(sb), 1e-5f);
            float n2  = fminf(nn, 2.3f);
            float scn = SC * n2;
            float th  = tanhf(scn);
            float f   = __fdividef(th, scn) * fminf(1.0f, __fdividef(2.3f, nn));
#pragma unroll
            for (int c = 0; c < 16; c++) shB[base + c] *= f;
            if (q == 0) shB2[row] = th * th * 10.0f;
        }

        if (gen) {
            // present[row] = any(Tsp == s0+row); quad splits the 1024 scan
            int target = s0 + row;
            int fnd = 0;
            const int* p = &shTsp[q * 256];
            for (int t = 0; t < 256; t++) fnd |= (p[t] == target);
            fnd |= __shfl_xor_sync(0xffffffffu, fnd, 1);
            fnd |= __shfl_xor_sync(0xffffffffu, fnd, 2);
            if (q == 0) shPr[row] = fnd;
        }
    }
    __syncthreads();

    // ---- GEMM: thread (tx,ty) owns rows {ty+16i}, cols {tx+16j}, f32x2 over k
    const int tx = tid & 15, ty = tid >> 4;
    ull acc[16];
#pragma unroll
    for (int u = 0; u < 16; u++) acc[u] = 0ull;

    const float* pa = shA + ty * LDST;
    const float* pb = shB + tx * LDST;
#pragma unroll 8
    for (int kk = 0; kk < 32; kk++) {
        ull a[4], b[4];
#pragma unroll
        for (int i = 0; i < 4; i++) a[i] = *(const ull*)(pa + i * 16 * LDST + 2 * kk);
#pragma unroll
        for (int j = 0; j < 4; j++) b[j] = *(const ull*)(pb + j * 16 * LDST + 2 * kk);
#pragma unroll
        for (int i = 0; i < 4; i++)
#pragma unroll
            for (int j = 0; j < 4; j++)
                asm("fma.rn.f32x2 %0, %1, %2, %0;"
                    : "+l"(acc[i * 4 + j]) : "l"(a[i]), "l"(b[j]));
    }

    // ---- epilogue ----
    float S1 = 0.0f, S2 = 0.0f;
#pragma unroll
    for (int i = 0; i < 4; i++) {
        int rl = ty + 16 * i;
        float a2 = shA2[rl];
        int   ti = shTi[rl];
        int   pr = gen ? shPr[rl] : 1;
#pragma unroll
        for (int j = 0; j < 4; j++) {
            int cl = tx + 16 * j;
            float lo, hi;
            asm("mov.b64 {%0, %1}, %2;" : "=f"(lo), "=f"(hi) : "l"(acc[i * 4 + j]));
            float dot = lo + hi;
            bool active  = gen ? (pr && cl < N_G) : true;
            bool matched = gen ? (ti == cl) : (ti == s0 + cl);
            if (active) pair_acc(dot, a2, shB2[cl], matched, S1, S2);
        }
    }
    S1 = warpsum(S1); S2 = warpsum(S2);
    int w = tid >> 5;
    if ((tid & 31) == 0) { red[w] = S1; red[w + 8] = S2; }
    __syncthreads();
    if (tid == 0) {
        float a = 0.0f, b = 0.0f;
#pragma unroll
        for (int q = 0; q < 8; q++) { a += red[q]; b += red[q + 8]; }
        g_part[blockIdx.x] = make_float2(a, b);
    }
}

// ---------------------------------------------------------------------------
// k_final: nvs = |{Tsp}|, nvg = |{s2g[Tsp]}| via shared bitmaps; deterministic
// double reduction of the 1088 per-block partials; write scalar loss.
// ---------------------------------------------------------------------------
__global__ void k_final(const int* __restrict__ Tsp, const int* __restrict__ s2g,
                        float* __restrict__ out)
{
    __shared__ unsigned int bm[128];
    __shared__ unsigned int bg[2];
    __shared__ double dr1[8], dr2[8], dr3[8], dr4[8];

    int tid = threadIdx.x;
    if (tid < 128) bm[tid] = 0u;
    if (tid < 2)   bg[tid] = 0u;
    __syncthreads();

    for (int b = tid; b < N_B; b += 256) {
        int s = Tsp[b];
        atomicOr(&bm[s >> 5], 1u << (s & 31));
        int g = s2g[s];
        atomicOr(&bg[g >> 5], 1u << (g & 31));
    }
    __syncthreads();

    double s1 = 0.0, s2 = 0.0, s3 = 0.0, s4 = 0.0;
    for (int i = tid; i < 1024; i += 256) {
        float2 v = g_part[i];
        s1 += (double)v.x; s2 += (double)v.y;
    }
    if (tid < 64) {
        float2 v = g_part[1024 + tid];
        s3 = (double)v.x; s4 = (double)v.y;
    }
    s1 = warpsumd(s1); s2 = warpsumd(s2);
    s3 = warpsumd(s3); s4 = warpsumd(s4);
    int w = tid >> 5;
    if ((tid & 31) == 0) { dr1[w] = s1; dr2[w] = s2; dr3[w] = s3; dr4[w] = s4; }
    __syncthreads();

    if (tid == 0) {
        double a1 = 0, a2 = 0, a3 = 0, a4 = 0;
#pragma unroll
        for (int q = 0; q < 8; q++) { a1 += dr1[q]; a2 += dr2[q]; a3 += dr3[q]; a4 += dr4[q]; }
        int nvs = 0;
        for (int q = 0; q < 128; q++) nvs += __popc(bm[q]);
        int nvg = __popc(bg[0]) + __popc(bg[1]);
        double loss = a1 / fmax((double)nvs, 1.0)
                    + a2 / (double)N_S
                    + a3 / fmax((double)nvg, 1.0)
                    + a4 / (double)N_G;
        out[0] = (float)loss;
    }
}

// ---------------------------------------------------------------------------
extern "C" void kernel_launch(void* const* d_in, const int* in_sizes, int n_in,
                              void* d_out, int out_size)
{
    (void)in_sizes; (void)n_in; (void)out_size;
    const float* X    = (const float*)d_in[0];
    const int*   Tsp  = (const int*)  d_in[1];
    // d_in[2] = T_genus (unused by the loss)
    const int*   s2g  = (const int*)  d_in[3];
    const float* gtan = (const float*)d_in[4];
    const float* stan = (const float*)d_in[5];

    k_main<<<1024 + 64, 256>>>(X, Tsp, s2g, gtan, stan);
    k_final<<<1, 256>>>(Tsp, s2g, (float*)d_out);
}